// round 15
// baseline (speedup 1.0000x reference)
#include <cuda_runtime.h>
#include <cuda_fp16.h>
#include <cstdint>

#define B_TOK 16384
#define N_CB  8192
#define DIM   512
#define MT    128          // tokens per CTA
#define NTILE 128          // codes per n-tile
#define KCH   64           // k per chunk
#define KCHUNKS 8          // DIM/KCH
#define TILES (N_CB/NTILE) // 64
#define NCHTOT (TILES*KCHUNKS)   // 512
#define NTHREADS 512
#define NWARPS  16
#define MARGIN 0.25f
#define CAP   32
#define CHUNK_BYTES 16384
#define BLOCK_BYTES (KCHUNKS*CHUNK_BYTES)   // 131072

// ---- global scratch: PRE-SWIZZLED chunk-blocked fp16 operands ----
__device__ __align__(128) uint8_t g_xh2[(size_t)(B_TOK/MT) * BLOCK_BYTES];  // 16 MB
__device__ __align__(128) uint8_t g_ch2[(size_t)TILES * BLOCK_BYTES];       //  8 MB
__device__ __align__(128) float   g_c2[N_CB];

// ---- SMEM layout (bytes) ----
#define SM_C2   0          // 128 f32 -> 512
#define SM_MAX  512        // 128 u32 -> 1024
#define SM_CNT  1024       // 128 u32 -> 1536
#define SM_IDX  1536       // 128 u32 -> 2048
#define SM_MBAR 2048       // mbar A @+0, B0 @+8, B1 @+16  -> 2560 (pad)
#define SM_LST  2560       // 128*CAP u32 = 16384 -> 18944
#define SM_A    18944      // 131072 -> 150016   (128B aligned)
#define SM_B    150016     // 2 x 16384 -> 182784
#define SMEM_TOTAL 182784

// ---------------- helpers ----------------
__device__ __forceinline__ uint32_t smem_u32(const void* p) {
    uint32_t a;
    asm("{ .reg .u64 t; cvta.to.shared.u64 t, %1; cvt.u32.u64 %0, t; }" : "=r"(a) : "l"(p));
    return a;
}
__device__ __forceinline__ void mbar_init(uint32_t m, uint32_t cnt) {
    asm volatile("mbarrier.init.shared.b64 [%0], %1;" :: "r"(m), "r"(cnt) : "memory");
}
__device__ __forceinline__ void mbar_expect_tx(uint32_t m, uint32_t bytes) {
    asm volatile("mbarrier.arrive.expect_tx.shared.b64 _, [%0], %1;"
                 :: "r"(m), "r"(bytes) : "memory");
}
__device__ __forceinline__ void mbar_wait(uint32_t m, uint32_t parity) {
    asm volatile(
        "{\n\t.reg .pred P1;\n\t"
        "WL_%=:\n\t"
        "mbarrier.try_wait.parity.shared.b64 P1, [%0], %1;\n\t"
        "@P1 bra WD_%=;\n\t"
        "bra WL_%=;\n\t"
        "WD_%=:\n\t}"
        :: "r"(m), "r"(parity) : "memory");
}
__device__ __forceinline__ void bulk_g2s(uint32_t dst, const void* src, uint32_t bytes, uint32_t mbar) {
    asm volatile("cp.async.bulk.shared::cluster.global.mbarrier::complete_tx::bytes "
                 "[%0], [%1], %2, [%3];"
                 :: "r"(dst), "l"(src), "r"(bytes), "r"(mbar) : "memory");
}
__device__ __forceinline__ void ldsm4(uint32_t* r, uint32_t addr) {
    asm volatile("ldmatrix.sync.aligned.m8n8.x4.shared.b16 {%0,%1,%2,%3}, [%4];"
                 : "=r"(r[0]), "=r"(r[1]), "=r"(r[2]), "=r"(r[3]) : "r"(addr));
}
__device__ __forceinline__ void mma16816(float* d, const uint32_t* a, uint32_t b0, uint32_t b1) {
    asm volatile("mma.sync.aligned.m16n8k16.row.col.f32.f16.f16.f32 "
                 "{%0,%1,%2,%3}, {%4,%5,%6,%7}, {%8,%9}, {%0,%1,%2,%3};"
                 : "+f"(d[0]), "+f"(d[1]), "+f"(d[2]), "+f"(d[3])
                 : "r"(a[0]), "r"(a[1]), "r"(a[2]), "r"(a[3]), "r"(b0), "r"(b1));
}
__device__ __forceinline__ uint32_t sw128(uint32_t off) { return off ^ ((off >> 3) & 0x70); }
__device__ __forceinline__ uint32_t enc32(float s) {
    uint32_t u = __float_as_uint(s);
    return (u & 0x80000000u) ? ~u : (u | 0x80000000u);
}
__device__ __forceinline__ float dec32(uint32_t v) {
    return (v & 0x80000000u) ? __uint_as_float(v ^ 0x80000000u) : __uint_as_float(~v);
}
__device__ __forceinline__ unsigned long long pack_key(float t, unsigned n) {
    return ((unsigned long long)enc32(t) << 32) | (unsigned long long)(0xFFFFFFFFu - n);
}

// ---------------- pre-kernels ----------------
__global__ void c2_kernel(const float* __restrict__ cb) {
    int row  = blockIdx.x * blockDim.y + threadIdx.y;
    int lane = threadIdx.x;
    const float4* r = (const float4*)(cb + (size_t)row * DIM);
    float s = 0.f;
#pragma unroll
    for (int i = 0; i < 4; i++) {
        float4 v = r[lane + 32 * i];
        s += v.x*v.x + v.y*v.y + v.z*v.z + v.w*v.w;
    }
#pragma unroll
    for (int off = 16; off > 0; off >>= 1) s += __shfl_down_sync(0xFFFFFFFFu, s, off);
    if (lane == 0) g_c2[row] = s;
}

// repack fp32 [rows x 512] -> fp16 chunk-blocked SW128-pre-swizzled layout
__global__ void repack_kernel(const float* __restrict__ src, uint8_t* __restrict__ dst, int nunits) {
    int i = blockIdx.x * blockDim.x + threadIdx.x;   // one 16B output unit
    if (i >= nunits) return;
    int blk = i >> 13;                 // 8192 units per 128-row block
    int rem = i & 8191;
    int c = rem >> 10, rem2 = rem & 1023, r = rem2 >> 3, u = rem2 & 7;
    const float4* s4 = (const float4*)(src + ((size_t)(blk * MT + r) * DIM + c * KCH + u * 8));
    float4 v0 = s4[0], v1 = s4[1];
    uint4 o;
    __half2 h;
    h = __floats2half2_rn(v0.x, v0.y); o.x = *(uint32_t*)&h;
    h = __floats2half2_rn(v0.z, v0.w); o.y = *(uint32_t*)&h;
    h = __floats2half2_rn(v1.x, v1.y); o.z = *(uint32_t*)&h;
    h = __floats2half2_rn(v1.z, v1.w); o.w = *(uint32_t*)&h;
    *(uint4*)(dst + (size_t)blk * BLOCK_BYTES + c * CHUNK_BYTES + sw128(r * 128 + u * 16)) = o;
}

// ---------------- main fused kernel ----------------
__global__ __launch_bounds__(NTHREADS, 1)
void vq_kernel(const float* __restrict__ x, const float* __restrict__ cb,
               const float* __restrict__ emb, float* __restrict__ out) {
    extern __shared__ char smem[];
    const uint32_t sb = smem_u32(smem);
    const int tid  = threadIdx.x;
    const int wid  = tid >> 5;
    const int lane = tid & 31;
    const int m0   = blockIdx.x * MT;
    const int wm   = wid & 3;       // m-group: rows wm*32 .. +31
    const int wn   = wid >> 2;      // n-group: cols wn*32 .. +31

    float*    c2s  = (float*)(smem + SM_C2);
    uint32_t* rmax = (uint32_t*)(smem + SM_MAX);
    uint32_t* cnt  = (uint32_t*)(smem + SM_CNT);
    uint32_t* idxs = (uint32_t*)(smem + SM_IDX);
    uint32_t* lst  = (uint32_t*)(smem + SM_LST);
    const uint32_t mbA  = sb + SM_MBAR;
    const uint32_t mbB0 = sb + SM_MBAR + 8;
    const uint32_t mbB1 = sb + SM_MBAR + 16;

    if (tid < MT) { rmax[tid] = 0u; cnt[tid] = 0u; }
    if (tid == 0) { mbar_init(mbA, 1); mbar_init(mbB0, 1); mbar_init(mbB1, 1); }
    __syncthreads();

    // ---- prologue: A (8 bulk copies) + B chunks 0,1 via TMA bulk ----
    if (tid == 0) {
        mbar_expect_tx(mbA, BLOCK_BYTES);
        const uint8_t* asrc = g_xh2 + (size_t)blockIdx.x * BLOCK_BYTES;
#pragma unroll
        for (int i = 0; i < KCHUNKS; i++)
            bulk_g2s(sb + SM_A + i * CHUNK_BYTES, asrc + i * CHUNK_BYTES, CHUNK_BYTES, mbA);
        mbar_expect_tx(mbB0, CHUNK_BYTES);
        bulk_g2s(sb + SM_B, g_ch2, CHUNK_BYTES, mbB0);
        mbar_expect_tx(mbB1, CHUNK_BYTES);
        bulk_g2s(sb + SM_B + CHUNK_BYTES, g_ch2 + CHUNK_BYTES, CHUNK_BYTES, mbB1);
    }
    mbar_wait(mbA, 0);                 // A resident

    // per-thread ldmatrix address components (byte offsets inside a chunk)
    const int rowA[2] = { wm*32 + (lane & 15), wm*32 + 16 + (lane & 15) };
    const int kuA = (lane >> 4) * 16;                         // 0 or 16 bytes
    const int rowB = wn*32 + (lane & 7) + ((lane >> 4) << 3); // x4 covers 16 n-rows
    const int kuB = ((lane >> 3) & 1) * 16;

    float acc[2][4][4];

    for (int t = 0; t < TILES; t++) {
        if (tid < NTILE) c2s[tid] = g_c2[t * NTILE + tid];

#pragma unroll
        for (int mf = 0; mf < 2; mf++)
#pragma unroll
            for (int nf = 0; nf < 4; nf++)
#pragma unroll
                for (int k = 0; k < 4; k++) acc[mf][nf][k] = 0.f;

        for (int c = 0; c < KCHUNKS; c++) {
            const int g = t * KCHUNKS + c;
            const int buf = g & 1;
            mbar_wait(buf ? mbB1 : mbB0, (g >> 1) & 1);   // chunk g data ready

            const uint32_t abase = sb + SM_A + c * CHUNK_BYTES;
            const uint32_t bbase = sb + SM_B + buf * CHUNK_BYTES;
#pragma unroll
            for (int ks = 0; ks < 4; ks++) {
                uint32_t a[2][4], b[2][4];
#pragma unroll
                for (int mf = 0; mf < 2; mf++)
                    ldsm4(a[mf], abase + sw128(rowA[mf] * 128 + ks * 32 + kuA));
#pragma unroll
                for (int gg = 0; gg < 2; gg++)
                    ldsm4(b[gg], bbase + sw128((rowB + gg * 16) * 128 + ks * 32 + kuB));
#pragma unroll
                for (int mf = 0; mf < 2; mf++)
#pragma unroll
                    for (int nf = 0; nf < 4; nf++)
                        mma16816(acc[mf][nf], a[mf],
                                 b[nf >> 1][(nf & 1) * 2], b[nf >> 1][(nf & 1) * 2 + 1]);
            }
            __syncthreads();                       // all warps done reading buf
            if (tid == 0 && g + 2 < NCHTOT) {      // refill same buf with chunk g+2
                uint32_t mb = buf ? mbB1 : mbB0;
                mbar_expect_tx(mb, CHUNK_BYTES);
                bulk_g2s(bbase, g_ch2 + (size_t)(g + 2) * CHUNK_BYTES, CHUNK_BYTES, mb);
            }
        }

        // ---- epilogue: running max ----
#pragma unroll
        for (int mf = 0; mf < 2; mf++)
#pragma unroll
            for (int rr = 0; rr < 2; rr++) {
                int row = wm*32 + mf*16 + (lane >> 2) + rr*8;
                float rb = -3.4e38f;
#pragma unroll
                for (int nf = 0; nf < 4; nf++)
#pragma unroll
                    for (int cc = 0; cc < 2; cc++) {
                        int col = wn*32 + nf*8 + (lane & 3)*2 + cc;
                        float s = fmaf(2.f, acc[mf][nf][rr*2 + cc], -c2s[col]);
                        if (s > rb) rb = s;
                    }
                atomicMax(&rmax[row], enc32(rb));
            }
        __syncthreads();

        // ---- admission: candidates within MARGIN of running max ----
#pragma unroll
        for (int mf = 0; mf < 2; mf++)
#pragma unroll
            for (int rr = 0; rr < 2; rr++) {
                int row = wm*32 + mf*16 + (lane >> 2) + rr*8;
                float thr = dec32(rmax[row]) - MARGIN;
#pragma unroll
                for (int nf = 0; nf < 4; nf++)
#pragma unroll
                    for (int cc = 0; cc < 2; cc++) {
                        int col = wn*32 + nf*8 + (lane & 3)*2 + cc;
                        float s = fmaf(2.f, acc[mf][nf][rr*2 + cc], -c2s[col]);
                        if (s >= thr) {
                            uint32_t slot = atomicAdd(&cnt[row], 1u);
                            if (slot < CAP) lst[row * CAP + slot] = (uint32_t)(t * NTILE + col);
                        }
                    }
            }
        __syncthreads();
    }

    // ---- phase 2: exact fp32 rescore of candidates ----
    for (int row = wid; row < MT; row += NWARPS) {
        unsigned n = cnt[row];
        unsigned long long bestk = 0ULL;
        const float* xr = x + (size_t)(m0 + row) * DIM;
        if (n == 0 || n > CAP) {
            for (int code = 0; code < N_CB; code++) {     // exact fallback (never on this data)
                const float* cr = cb + (size_t)code * DIM;
                float p = 0.f;
                for (int e = lane; e < DIM; e += 32) p = fmaf(xr[e], cr[e], p);
#pragma unroll
                for (int off = 16; off > 0; off >>= 1) p += __shfl_xor_sync(0xFFFFFFFFu, p, off);
                unsigned long long k = pack_key(fmaf(2.f, p, -g_c2[code]), (unsigned)code);
                if (k > bestk) bestk = k;
            }
        } else {
            for (unsigned j = 0; j < n; j++) {
                unsigned code = lst[row * CAP + j];
                const float* cr = cb + (size_t)code * DIM;
                float p = 0.f;
#pragma unroll
                for (int e = 0; e < DIM / 32; e++) p = fmaf(xr[lane + 32*e], cr[lane + 32*e], p);
#pragma unroll
                for (int off = 16; off > 0; off >>= 1) p += __shfl_xor_sync(0xFFFFFFFFu, p, off);
                unsigned long long k = pack_key(fmaf(2.f, p, -g_c2[code]), code);
                if (k > bestk) bestk = k;
            }
        }
        if (lane == 0) idxs[row] = 0xFFFFFFFFu - (uint32_t)(bestk & 0xFFFFFFFFu);
    }
    __syncthreads();

    // ---- gather: out[m] = embedding[idx[m]] ----
    const float4* e4 = (const float4*)emb;
    float4* o4 = (float4*)out;
    for (int i = tid; i < MT * (DIM / 4); i += NTHREADS) {
        int m = i >> 7, cc = i & 127;
        o4[(size_t)(m0 + m) * (DIM / 4) + cc] = e4[(size_t)idxs[m] * (DIM / 4) + cc];
    }
}

// ---------------------------------------------------------------------------
extern "C" void kernel_launch(void* const* d_in, const int* in_sizes, int n_in,
                              void* d_out, int out_size) {
    const float* x   = (const float*)d_in[0];
    const float* cb  = (const float*)d_in[1];
    const float* emb = (const float*)d_in[2];
    float* out = (float*)d_out;

    cudaFuncSetAttribute(vq_kernel, cudaFuncAttributeMaxDynamicSharedMemorySize, SMEM_TOTAL);

    uint8_t *xh2, *ch2;
    cudaGetSymbolAddress((void**)&xh2, g_xh2);
    cudaGetSymbolAddress((void**)&ch2, g_ch2);

    repack_kernel<<<(B_TOK*DIM*2/16 + 255)/256, 256>>>(x,  xh2, B_TOK*DIM*2/16);
    repack_kernel<<<(N_CB*DIM*2/16 + 255)/256, 256>>>(cb, ch2, N_CB*DIM*2/16);
    c2_kernel<<<N_CB/8, dim3(32, 8)>>>(cb);
    vq_kernel<<<B_TOK/MT, NTHREADS, SMEM_TOTAL>>>(x, cb, emb, out);
}